// round 3
// baseline (speedup 1.0000x reference)
#include <cuda_runtime.h>
#include <math.h>

// VectorQuantizer: N=131072 rows (dim 64) vs 512 codes (dim 64).
// Out (float32): [0,8388608) quantized_st; [8388608,8519680) codes;
//                then commitment*0.25, codebook_loss, perplexity.
//
// Argmin must be bitwise-identical to the reference fp32 pipeline:
//   mm  = sequential fma chain d=0..63
//   x2,c2 = sequential sum of round(v*v)
//   d2  = round( round(x2 - 2*mm) + c2 ), argmin = first-min.
// Fast path uses packed fma.rn.f32x2 (2 interleaved chains) which is NOT
// bitwise-identical, so ambiguous rows (top-2 approx gap <= EPS) are
// re-scored with the exact sequential chain. EPS bounds the max possible
// approx-vs-exact score deviation (grid ulp(x2) + chain divergence, 2x).
#define K_CODES 512
#define DIMV 64
#define NROWS 131072
#define TPB 256
#define NBLK 148
#define ROWS_PER_BLK ((NROWS + NBLK - 1) / NBLK)   // 886
#define EPS 6e-5f

typedef unsigned long long ull;

__device__ double g_sqsum;
__device__ int g_counts[K_CODES];

__device__ __forceinline__ float lof(ull p) { return __int_as_float((int)(unsigned)p); }
__device__ __forceinline__ float hif(ull p) { return __int_as_float((int)(unsigned)(p >> 32)); }
__device__ __forceinline__ ull pk(float a, float b) {
    ull r; asm("mov.b64 %0, {%1, %2};" : "=l"(r) : "f"(a), "f"(b)); return r;
}
__device__ __forceinline__ void ffma2(ull& d, ull a, ull b) {
    asm("fma.rn.f32x2 %0, %1, %2, %0;" : "+l"(d) : "l"(a), "l"(b));
}

__global__ void vq_init_kernel() {
    int t = blockIdx.x * blockDim.x + threadIdx.x;
    if (t == 0) g_sqsum = 0.0;
    if (t < K_CODES) g_counts[t] = 0;
}

// Exact reference-order score: sequential fma chain d=0..63, then
// round(round(x2 - 2mm) + c2).
__device__ __forceinline__ float exact_score(const float* __restrict__ c,
                                             float c2, const ull* xp, float x2) {
    float m = 0.f;
    #pragma unroll
    for (int j = 0; j < 32; ++j) {
        m = __fmaf_rn(lof(xp[j]), c[2 * j], m);
        m = __fmaf_rn(hif(xp[j]), c[2 * j + 1], m);
    }
    return __fadd_rn(__fadd_rn(x2, -2.f * m), c2);
}

// Rare path: exact first-min over all 512 codes (ILP-4 across codes; each
// code's chain stays strictly sequential).
__device__ __noinline__ int exact_scan_all(const float* __restrict__ scb,
                                           const float* __restrict__ sc2,
                                           const ull* xp, float x2) {
    float best = 3.4e38f; int bk = 0;
    for (int k = 0; k < K_CODES; k += 4) {
        float m0 = 0.f, m1 = 0.f, m2 = 0.f, m3 = 0.f;
        const float* c0 = scb + (k + 0) * DIMV;
        const float* c1 = scb + (k + 1) * DIMV;
        const float* c2p = scb + (k + 2) * DIMV;
        const float* c3 = scb + (k + 3) * DIMV;
        #pragma unroll
        for (int j = 0; j < 32; ++j) {
            float a = lof(xp[j]), b = hif(xp[j]);
            m0 = __fmaf_rn(a, c0[2 * j], m0); m0 = __fmaf_rn(b, c0[2 * j + 1], m0);
            m1 = __fmaf_rn(a, c1[2 * j], m1); m1 = __fmaf_rn(b, c1[2 * j + 1], m1);
            m2 = __fmaf_rn(a, c2p[2 * j], m2); m2 = __fmaf_rn(b, c2p[2 * j + 1], m2);
            m3 = __fmaf_rn(a, c3[2 * j], m3); m3 = __fmaf_rn(b, c3[2 * j + 1], m3);
        }
        float s;
        s = __fadd_rn(__fadd_rn(x2, -2.f * m0), sc2[k + 0]); if (s < best) { best = s; bk = k + 0; }
        s = __fadd_rn(__fadd_rn(x2, -2.f * m1), sc2[k + 1]); if (s < best) { best = s; bk = k + 1; }
        s = __fadd_rn(__fadd_rn(x2, -2.f * m2), sc2[k + 2]); if (s < best) { best = s; bk = k + 2; }
        s = __fadd_rn(__fadd_rn(x2, -2.f * m3), sc2[k + 3]); if (s < best) { best = s; bk = k + 3; }
    }
    return bk;
}

__global__ __launch_bounds__(TPB, 1)
void vq_main_kernel(const float* __restrict__ latents,
                    const float* __restrict__ codebook,
                    float* __restrict__ out) {
    extern __shared__ float smem[];
    float* scb   = smem;                        // 512*64 floats (natural layout)
    float* sc2   = smem + K_CODES * DIMV;       // 512
    int*   shist = (int*)(sc2 + K_CODES);       // 512
    float* sred  = (float*)(shist + K_CODES);   // TPB

    const float4* cb4 = (const float4*)codebook;
    float4* scb4 = (float4*)scb;
    for (int i = threadIdx.x; i < K_CODES * DIMV / 4; i += TPB)
        scb4[i] = cb4[i];
    for (int k = threadIdx.x; k < K_CODES; k += TPB) shist[k] = 0;
    __syncthreads();
    for (int k = threadIdx.x; k < K_CODES; k += TPB) {
        float s = 0.f;
        const float* c = scb + k * DIMV;
        #pragma unroll
        for (int d = 0; d < DIMV; ++d) s = __fadd_rn(s, __fmul_rn(c[d], c[d]));
        sc2[k] = s;
    }
    __syncthreads();

    const int row0 = blockIdx.x * ROWS_PER_BLK;
    const int rowEnd = min(row0 + ROWS_PER_BLK, NROWS);

    float sqAcc = 0.f;   // per-thread loss partial across rows

    for (int row = row0 + threadIdx.x; row < rowEnd; row += TPB) {
        // Load latent row packed: xp[j] = (x[2j], x[2j+1]).
        ull xp[32];
        const float4* lp = (const float4*)(latents + (size_t)row * DIMV);
        #pragma unroll
        for (int i = 0; i < 16; ++i) {
            float4 t = lp[i];
            xp[2 * i]     = pk(t.x, t.y);
            xp[2 * i + 1] = pk(t.z, t.w);
        }
        // x2 in exact sequential order d=0..63.
        float x2 = 0.f;
        #pragma unroll
        for (int j = 0; j < 32; ++j) {
            float a = lof(xp[j]), b = hif(xp[j]);
            x2 = __fadd_rn(x2, __fmul_rn(a, a));
            x2 = __fadd_rn(x2, __fmul_rn(b, b));
        }

        // Pass 1: packed-FMA scores, track 3 smallest.
        float s0 = 3.4e38f, s1 = 3.4e38f, s2v = 3.4e38f;
        int k0 = 0, k1 = 0, k2 = 0;
        for (int kb = 0; kb < K_CODES; kb += 8) {
            ull acc[8];
            #pragma unroll
            for (int j = 0; j < 8; ++j) acc[j] = 0ull;
            #pragma unroll
            for (int i = 0; i < 16; ++i) {
                const ull xa = xp[2 * i], xb = xp[2 * i + 1];
                #pragma unroll
                for (int j = 0; j < 8; ++j) {
                    ulonglong2 c = ((const ulonglong2*)(scb + (kb + j) * DIMV))[i];
                    ffma2(acc[j], xa, c.x);
                    ffma2(acc[j], xb, c.y);
                }
            }
            #pragma unroll
            for (int j = 0; j < 8; ++j) {
                float mm = __fadd_rn(lof(acc[j]), hif(acc[j]));
                float s = __fadd_rn(__fadd_rn(x2, -2.f * mm), sc2[kb + j]);
                if (s < s2v) {
                    if (s < s1) {
                        if (s < s0) { s2v = s1; k2 = k1; s1 = s0; k1 = k0; s0 = s; k0 = kb + j; }
                        else        { s2v = s1; k2 = k1; s1 = s;  k1 = kb + j; }
                    } else          { s2v = s;  k2 = kb + j; }
                }
            }
        }
        (void)k2;

        // Pass 2: disambiguate with exact reference-order arithmetic.
        int bestk = k0;
        if (s1 - s0 <= EPS) {
            if (s2v - s0 <= EPS) {
                bestk = exact_scan_all(scb, sc2, xp, x2);
            } else {
                float e0 = exact_score(scb + k0 * DIMV, sc2[k0], xp, x2);
                float e1 = exact_score(scb + k1 * DIMV, sc2[k1], xp, x2);
                int ka = min(k0, k1), kb2 = max(k0, k1);
                float ea = (k0 < k1) ? e0 : e1;
                float eb = (k0 < k1) ? e1 : e0;
                bestk = (eb < ea) ? kb2 : ka;   // first-min on tie
            }
        }

        // Epilogue: ST output (reference roundings), loss partial, histogram.
        float* qout = out + (size_t)row * DIMV;
        const float* cq = scb + bestk * DIMV;
        float rowsq = 0.f;
        #pragma unroll
        for (int i = 0; i < 16; ++i) {
            float lx = lof(xp[2 * i]),     ly = hif(xp[2 * i]);
            float lz = lof(xp[2 * i + 1]), lw = hif(xp[2 * i + 1]);
            float qx = cq[4 * i], qy = cq[4 * i + 1], qz = cq[4 * i + 2], qw = cq[4 * i + 3];
            float4 o;
            o.x = __fadd_rn(lx, __fsub_rn(qx, lx));
            o.y = __fadd_rn(ly, __fsub_rn(qy, ly));
            o.z = __fadd_rn(lz, __fsub_rn(qz, lz));
            o.w = __fadd_rn(lw, __fsub_rn(qw, lw));
            float dx = lx - qx, dy = ly - qy, dz = lz - qz, dw = lw - qw;
            rowsq = fmaf(dx, dx, rowsq);
            rowsq = fmaf(dy, dy, rowsq);
            rowsq = fmaf(dz, dz, rowsq);
            rowsq = fmaf(dw, dw, rowsq);
            ((float4*)qout)[i] = o;
        }
        out[(size_t)NROWS * DIMV + row] = (float)bestk;
        atomicAdd(&shist[bestk], 1);
        sqAcc += rowsq;
    }

    // Block reduction of loss partial + histogram flush.
    sred[threadIdx.x] = sqAcc;
    __syncthreads();
    for (int s = TPB / 2; s > 0; s >>= 1) {
        if (threadIdx.x < s) sred[threadIdx.x] += sred[threadIdx.x + s];
        __syncthreads();
    }
    if (threadIdx.x == 0) atomicAdd(&g_sqsum, (double)sred[0]);
    for (int k = threadIdx.x; k < K_CODES; k += TPB) {
        int c = shist[k];
        if (c) atomicAdd(&g_counts[k], c);
    }
}

__global__ void vq_finalize_kernel(float* __restrict__ out) {
    __shared__ float red[K_CODES];
    int t = threadIdx.x;
    float p = (float)g_counts[t] / (float)NROWS;
    red[t] = -p * logf(p + 1e-10f);
    __syncthreads();
    for (int s = K_CODES / 2; s > 0; s >>= 1) {
        if (t < s) red[t] += red[t + s];
        __syncthreads();
    }
    if (t == 0) {
        float perp = expf(red[0]);
        float msd = (float)(g_sqsum / (double)((size_t)NROWS * DIMV));
        size_t base = (size_t)NROWS * DIMV + NROWS;
        out[base + 0] = msd * 0.25f;
        out[base + 1] = msd;
        out[base + 2] = perp;
    }
}

extern "C" void kernel_launch(void* const* d_in, const int* in_sizes, int n_in,
                              void* d_out, int out_size) {
    (void)in_sizes; (void)n_in; (void)out_size;
    const float* latents  = (const float*)d_in[0];
    const float* codebook = (const float*)d_in[1];
    float* out = (float*)d_out;

    const int smem_bytes = (K_CODES * DIMV) * 4 + K_CODES * 4 + K_CODES * 4 + TPB * 4;
    cudaFuncSetAttribute(vq_main_kernel,
                         cudaFuncAttributeMaxDynamicSharedMemorySize, smem_bytes);

    vq_init_kernel<<<2, 256>>>();
    vq_main_kernel<<<NBLK, TPB, smem_bytes>>>(latents, codebook, out);
    vq_finalize_kernel<<<1, K_CODES>>>(out);
}